// round 1
// baseline (speedup 1.0000x reference)
#include <cuda_runtime.h>

// LSTM_71683004170991 — only batch element B-1 contributes to the output:
//   reference returns sigmoid(h_final[-1] @ W_lin.T + b_lin)  -> 5 floats.
// So we run ONE sequential LSTM (T=512, I=5, H=16) in a single warp,
// after a parallel precompute of the input projection xp[t][g].

#define FULLMASK 0xffffffffu

namespace {
constexpr int Bn = 4096;
constexpr int Tn = 512;
constexpr int In = 5;
constexpr int Hn = 16;
constexpr int Gn = 4 * Hn;  // 64 gates

constexpr int XP_ELEMS = Tn * Gn;   // 32768
constexpr int X_ELEMS  = Tn * In;   // 2560
constexpr int W_ELEMS  = Gn * In;   // 320
// smem floats: xp + x + Wih + bias + h_final
constexpr int SMEM_FLOATS = XP_ELEMS + X_ELEMS + W_ELEMS + Gn + Hn;
}

__global__ __launch_bounds__(512, 1)
void lstm_last_kernel(const float* __restrict__ x,
                      const float* __restrict__ Wih,
                      const float* __restrict__ Whh,
                      const float* __restrict__ bih,
                      const float* __restrict__ bhh,
                      const float* __restrict__ Wlin,
                      const float* __restrict__ blin,
                      float* __restrict__ out)
{
    extern __shared__ float smem[];
    float* s_xp = smem;                    // [Tn][Gn]
    float* s_x  = s_xp + XP_ELEMS;         // [Tn][In]
    float* s_w  = s_x + X_ELEMS;           // [Gn][In]
    float* s_b  = s_w + W_ELEMS;           // [Gn]
    float* s_h  = s_b + Gn;                // [Hn]

    const int tid = threadIdx.x;

    // ---- Stage inputs for the last batch row ----
    const float* xrow = x + (size_t)(Bn - 1) * Tn * In;
    for (int i = tid; i < X_ELEMS; i += 512) s_x[i] = xrow[i];
    for (int i = tid; i < W_ELEMS; i += 512) s_w[i] = Wih[i];
    if (tid < Gn) s_b[tid] = bih[tid] + bhh[tid];
    __syncthreads();

    // ---- Phase 1 (parallel): xp[t][g] = x_t . W_ih[g] + b_ih[g] + b_hh[g] ----
    // Gate row order (PyTorch): rows 0..15 = i, 16..31 = f, 32..47 = g, 48..63 = o.
    for (int idx = tid; idx < XP_ELEMS; idx += 512) {
        const int t = idx >> 6;
        const int g = idx & 63;
        const float* xr = s_x + t * In;
        const float* wr = s_w + g * In;
        float v = s_b[g];
        #pragma unroll
        for (int i = 0; i < In; i++) v = fmaf(xr[i], wr[i], v);
        s_xp[idx] = v;
    }
    __syncthreads();

    // ---- Phase 2 (serial scan): warp 0 only ----
    // Lane layout: lane l (<16) owns unit l gates (i, g); lane l+16 owns (f, o).
    // h is replicated: lanes l and l+16 both hold h[l]; shfl reads lanes 0..15.
    if (tid < 32) {
        const int lane = tid;
        const bool lo = lane < 16;

        // Wa row = lane   (i rows 0..15 / f rows 16..31)
        // Wb row = 32+lane (g rows 32..47 / o rows 48..63)
        float Wa[Hn], Wb[Hn];
        #pragma unroll
        for (int k = 0; k < Hn; k++) {
            Wa[k] = Whh[lane * Hn + k];
            Wb[k] = Whh[(32 + lane) * Hn + k];
        }

        float h = 0.0f, c = 0.0f;
        // Unified activation params for gb: lo -> tanh, hi -> sigmoid.
        const float numc = lo ? -1.0f : 0.0f;   // numerator = numc*e + 1
        const float scl  = lo ? -2.0f : -1.0f;  // e = exp(scl * arg)

        for (int t = 0; t < Tn; t++) {
            float ga = s_xp[t * Gn + lane];        // i (lo) / f (hi)
            float gb = s_xp[t * Gn + 32 + lane];   // g (lo) / o (hi)

            #pragma unroll
            for (int k = 0; k < Hn; k++) {
                const float hk = __shfl_sync(FULLMASK, h, k);
                ga = fmaf(Wa[k], hk, ga);
                gb = fmaf(Wb[k], hk, gb);
            }

            // a = sigmoid(ga) on ALL lanes (i and f are both sigmoids)
            const float ea = __expf(-ga);
            const float a  = __fdividef(1.0f, 1.0f + ea);

            // b = tanh(gb) on lanes<16, sigmoid(gb) on lanes>=16 (overflow-safe)
            const float xb = lo ? fabsf(gb) : gb;
            const float eb = __expf(scl * xb);
            const float nb = fmaf(numc, eb, 1.0f);
            float b = __fdividef(nb, 1.0f + eb);
            if (lo) b = copysignf(b, gb);

            // Exchange across halves so both halves compute identical c, h.
            const float ax = __shfl_xor_sync(FULLMASK, a, 16);
            const float bx = __shfl_xor_sync(FULLMASK, b, 16);
            const float iv = lo ? a  : ax;
            const float fv = lo ? ax : a;
            const float gv = lo ? b  : bx;
            const float ov = lo ? bx : b;

            c = fmaf(fv, c, iv * gv);

            // tanh(c), overflow-safe
            const float ec = __expf(-2.0f * fabsf(c));
            float tc = __fdividef(1.0f - ec, 1.0f + ec);
            tc = copysignf(tc, c);

            h = ov * tc;
        }

        if (lo) s_h[lane] = h;
    }
    __syncthreads();

    // ---- Output: sigmoid(h_last @ W_lin.T + b_lin), 5 values ----
    if (tid < 5) {
        float v = blin[tid];
        #pragma unroll
        for (int k = 0; k < Hn; k++) v = fmaf(s_h[k], Wlin[tid * Hn + k], v);
        const float e = __expf(-v);
        out[tid] = __fdividef(1.0f, 1.0f + e);
    }
}

extern "C" void kernel_launch(void* const* d_in, const int* in_sizes, int n_in,
                              void* d_out, int out_size)
{
    // Identify inputs by element count (robust to metadata ordering).
    const float *x = nullptr, *Wih = nullptr, *Whh = nullptr;
    const float *bih = nullptr, *bhh = nullptr, *Wlin = nullptr, *blin = nullptr;
    for (int i = 0; i < n_in; i++) {
        const int s = in_sizes[i];
        const float* p = (const float*)d_in[i];
        if      (s == Bn * Tn * In) x    = p;   // 10485760
        else if (s == Gn * In)      Wih  = p;   // 320
        else if (s == Gn * Hn)      Whh  = p;   // 1024
        else if (s == 5 * Hn)       Wlin = p;   // 80
        else if (s == Gn)           { if (!bih) bih = p; else bhh = p; } // 64, 64
        else if (s == 5)            blin = p;   // 5
    }

    const size_t smem_bytes = (size_t)SMEM_FLOATS * sizeof(float); // ~143 KB
    cudaFuncSetAttribute(lstm_last_kernel,
                         cudaFuncAttributeMaxDynamicSharedMemorySize,
                         (int)smem_bytes);

    lstm_last_kernel<<<1, 512, smem_bytes>>>(
        x, Wih, Whh, bih, bhh, Wlin, blin, (float*)d_out);
}

// round 2
// speedup vs baseline: 1.5287x; 1.5287x over previous
#include <cuda_runtime.h>

// LSTM_71683004170991 — only batch element B-1 contributes to the output.
// Single-warp serial scan (T=512, H=16) after parallel xp precompute.
// R2: MUFU.TANH activations, split accumulators, product-exchange, xp prefetch.

#define FULLMASK 0xffffffffu

namespace {
constexpr int Bn = 4096;
constexpr int Tn = 512;
constexpr int In = 5;
constexpr int Hn = 16;
constexpr int Gn = 4 * Hn;  // 64 gates

constexpr int XP_ROWS  = Tn + 1;          // +1 zero pad row for prefetch
constexpr int XP_ELEMS = XP_ROWS * Gn;    // 32832
constexpr int X_ELEMS  = Tn * In;         // 2560
constexpr int W_ELEMS  = Gn * In;         // 320
constexpr int SMEM_FLOATS = XP_ELEMS + X_ELEMS + W_ELEMS + Gn + Hn;
}

__device__ __forceinline__ float tanh_apx(float x) {
    float y;
    asm("tanh.approx.f32 %0, %1;" : "=f"(y) : "f"(x));
    return y;
}

__global__ __launch_bounds__(512, 1)
void lstm_last_kernel(const float* __restrict__ x,
                      const float* __restrict__ Wih,
                      const float* __restrict__ Whh,
                      const float* __restrict__ bih,
                      const float* __restrict__ bhh,
                      const float* __restrict__ Wlin,
                      const float* __restrict__ blin,
                      float* __restrict__ out)
{
    extern __shared__ float smem[];
    float* s_xp = smem;                    // [XP_ROWS][Gn]
    float* s_x  = s_xp + XP_ELEMS;         // [Tn][In]
    float* s_w  = s_x + X_ELEMS;           // [Gn][In]
    float* s_b  = s_w + W_ELEMS;           // [Gn]
    float* s_h  = s_b + Gn;                // [Hn]

    const int tid = threadIdx.x;

    // ---- Stage inputs for the last batch row ----
    const float* xrow = x + (size_t)(Bn - 1) * Tn * In;
    for (int i = tid; i < X_ELEMS; i += 512) s_x[i] = xrow[i];
    for (int i = tid; i < W_ELEMS; i += 512) s_w[i] = Wih[i];
    if (tid < Gn) {
        s_b[tid] = bih[tid] + bhh[tid];
        s_xp[Tn * Gn + tid] = 0.0f;        // pad row (prefetch target at t=Tn-1)
    }
    __syncthreads();

    // ---- Phase 1 (parallel): xp[t][g] = x_t . W_ih[g] + b_ih[g] + b_hh[g] ----
    // PyTorch gate row order: 0..15 = i, 16..31 = f, 32..47 = g, 48..63 = o.
    for (int idx = tid; idx < Tn * Gn; idx += 512) {
        const int t = idx >> 6;
        const int g = idx & 63;
        const float* xr = s_x + t * In;
        const float* wr = s_w + g * In;
        float v = s_b[g];
        #pragma unroll
        for (int i = 0; i < In; i++) v = fmaf(xr[i], wr[i], v);
        s_xp[idx] = v;
    }
    __syncthreads();

    // ---- Phase 2 (serial scan): warp 0 only ----
    // Lane l (<16) owns unit l's (i, g); lane l+16 owns (f, o).
    // Both halves redundantly compute c and h, so every lane holds h[lane&15].
    if (tid < 32) {
        const int lane = tid;
        const bool lo = lane < 16;

        float Wa[Hn], Wb[Hn];
        #pragma unroll
        for (int k = 0; k < Hn; k++) {
            Wa[k] = Whh[lane * Hn + k];          // i rows / f rows
            Wb[k] = Whh[(32 + lane) * Hn + k];   // g rows / o rows
        }

        // lane-constant activation params for the b path:
        // lo: tanh(gb)            -> arg scale 1.0, out = 1.0*t + 0.0
        // hi: sigmoid(gb)         -> arg scale 0.5, out = 0.5*t + 0.5
        const float sb = lo ? 1.0f : 0.5f;
        const float cb = lo ? 1.0f : 0.5f;
        const float db = lo ? 0.0f : 0.5f;

        float h = 0.0f, c = 0.0f;
        float ga_in = s_xp[lane];
        float gb_in = s_xp[32 + lane];

        for (int t = 0; t < Tn; t++) {
            // prefetch next timestep's xp (pad row makes t=Tn-1 safe)
            const float nga = s_xp[(t + 1) * Gn + lane];
            const float ngb = s_xp[(t + 1) * Gn + 32 + lane];

            // gate accumulation, 2-way split accumulators
            float ga0 = ga_in, ga1 = 0.0f;
            float gb0 = gb_in, gb1 = 0.0f;
            #pragma unroll
            for (int k = 0; k < Hn; k += 2) {
                const float h0 = __shfl_sync(FULLMASK, h, k);
                const float h1 = __shfl_sync(FULLMASK, h, k + 1);
                ga0 = fmaf(Wa[k],     h0, ga0);
                ga1 = fmaf(Wa[k + 1], h1, ga1);
                gb0 = fmaf(Wb[k],     h0, gb0);
                gb1 = fmaf(Wb[k + 1], h1, gb1);
            }
            const float ga = ga0 + ga1;
            const float gb = gb0 + gb1;

            // a = sigmoid(ga) on all lanes (i | f)
            const float a = fmaf(0.5f, tanh_apx(0.5f * ga), 0.5f);
            // b = tanh(gb) on lo (g), sigmoid(gb) on hi (o)
            const float b = fmaf(cb, tanh_apx(sb * gb), db);

            // exchange: one shfl carries (lo: i*g, hi: f); second carries o.
            const float p  = a * b;                 // lo: i*g (used), hi: scratch
            const float s1 = lo ? p : a;
            const float r1 = __shfl_xor_sync(FULLMASK, s1, 16);
            const float r2 = __shfl_xor_sync(FULLMASK, b, 16);

            const float fv = lo ? r1 : a;
            const float ig = lo ? p  : r1;
            const float ov = lo ? r2 : b;

            c = fmaf(fv, c, ig);
            h = ov * tanh_apx(c);

            ga_in = nga;
            gb_in = ngb;
        }

        if (lo) s_h[lane] = h;
    }
    __syncthreads();

    // ---- Output: sigmoid(h_last @ W_lin.T + b_lin), 5 values ----
    if (tid < 5) {
        float v = blin[tid];
        #pragma unroll
        for (int k = 0; k < Hn; k++) v = fmaf(s_h[k], Wlin[tid * Hn + k], v);
        const float e = __expf(-v);
        out[tid] = __fdividef(1.0f, 1.0f + e);
    }
}

extern "C" void kernel_launch(void* const* d_in, const int* in_sizes, int n_in,
                              void* d_out, int out_size)
{
    const float *x = nullptr, *Wih = nullptr, *Whh = nullptr;
    const float *bih = nullptr, *bhh = nullptr, *Wlin = nullptr, *blin = nullptr;
    for (int i = 0; i < n_in; i++) {
        const int s = in_sizes[i];
        const float* p = (const float*)d_in[i];
        if      (s == Bn * Tn * In) x    = p;
        else if (s == Gn * In)      Wih  = p;
        else if (s == Gn * Hn)      Whh  = p;
        else if (s == 5 * Hn)       Wlin = p;
        else if (s == Gn)           { if (!bih) bih = p; else bhh = p; }
        else if (s == 5)            blin = p;
    }

    const size_t smem_bytes = (size_t)SMEM_FLOATS * sizeof(float);
    cudaFuncSetAttribute(lstm_last_kernel,
                         cudaFuncAttributeMaxDynamicSharedMemorySize,
                         (int)smem_bytes);

    lstm_last_kernel<<<1, 512, smem_bytes>>>(
        x, Wih, Whh, bih, bhh, Wlin, blin, (float*)d_out);
}

// round 3
// speedup vs baseline: 1.6338x; 1.0687x over previous
#include <cuda_runtime.h>

// LSTM_71683004170991 — only batch element B-1 contributes to the output.
// Single-warp serial scan (T=512, H=16) after parallel xp precompute.
// R3: smem ping-pong h-broadcast (replaces 16-shfl broadcast), packed
//     fma.rn.f32x2 gate accumulation, pre-scaled sigmoid arguments.

#define FULLMASK 0xffffffffu
typedef unsigned long long ull;

namespace {
constexpr int Bn = 4096;
constexpr int Tn = 512;
constexpr int In = 5;
constexpr int Hn = 16;
constexpr int Gn = 4 * Hn;  // 64

// smem float layout (16B-aligned blocks):
//   s_hb : 2 bufs x 16 pairs x 2 floats = 64 floats (ping-pong h broadcast)
//   s_xp : (Tn+1) rows x 32 pairs x 2 floats (pair p = (gate p, gate 32+p))
//   s_x  : Tn*In, s_w : Gn*In, s_b : Gn, s_h : Hn
constexpr int HB_FLOATS = 64;
constexpr int XP_FLOATS = (Tn + 1) * 64;   // 32832
constexpr int X_ELEMS   = Tn * In;         // 2560
constexpr int W_ELEMS   = Gn * In;         // 320
constexpr int SMEM_FLOATS = HB_FLOATS + XP_FLOATS + X_ELEMS + W_ELEMS + Gn + Hn;
}

__device__ __forceinline__ float tanh_apx(float x) {
    float y;
    asm("tanh.approx.f32 %0, %1;" : "=f"(y) : "f"(x));
    return y;
}
__device__ __forceinline__ void fma2(ull& d, ull a, ull b, ull c) {
    asm("fma.rn.f32x2 %0, %1, %2, %3;" : "=l"(d) : "l"(a), "l"(b), "l"(c));
}
__device__ __forceinline__ void add2(ull& d, ull a, ull b) {
    asm("add.rn.f32x2 %0, %1, %2;" : "=l"(d) : "l"(a), "l"(b));
}
__device__ __forceinline__ ull pack2(float lo, float hi) {
    ull d;
    asm("mov.b64 %0, {%1, %2};" : "=l"(d) : "f"(lo), "f"(hi));
    return d;
}
__device__ __forceinline__ void unpack2(float& lo, float& hi, ull v) {
    asm("mov.b64 {%0, %1}, %2;" : "=f"(lo), "=f"(hi) : "l"(v));
}

__global__ __launch_bounds__(512, 1)
void lstm_last_kernel(const float* __restrict__ x,
                      const float* __restrict__ Wih,
                      const float* __restrict__ Whh,
                      const float* __restrict__ bih,
                      const float* __restrict__ bhh,
                      const float* __restrict__ Wlin,
                      const float* __restrict__ blin,
                      float* __restrict__ out)
{
    extern __shared__ float smem[];
    float* s_hb = smem;                    // [2][16] pairs
    float* s_xp = s_hb + HB_FLOATS;        // [Tn+1][32] pairs
    float* s_x  = s_xp + XP_FLOATS;
    float* s_w  = s_x + X_ELEMS;
    float* s_b  = s_w + W_ELEMS;
    float* s_h  = s_b + Gn;

    const int tid = threadIdx.x;

    // ---- Stage inputs for the last batch row ----
    const float* xrow = x + (size_t)(Bn - 1) * Tn * In;
    for (int i = tid; i < X_ELEMS; i += 512) s_x[i] = xrow[i];
    for (int i = tid; i < W_ELEMS; i += 512) s_w[i] = Wih[i];
    if (tid < Gn) {
        s_b[tid] = bih[tid] + bhh[tid];
        s_xp[Tn * 64 + tid] = 0.0f;        // zero pad row (prefetch at t=Tn-1)
    }
    __syncthreads();

    // ---- Phase 1: xp'[t][g] = sc_g * (x_t . W_ih[g] + b_ih[g] + b_hh[g]) ----
    // Gate rows (PyTorch): 0..15 i, 16..31 f, 32..47 g, 48..63 o.
    // Sigmoid rows (i,f,o) pre-scaled by 0.5 for sigma(x)=0.5+0.5*tanh(x/2).
    // Pair layout: s_xp[t*64 + (g&31)*2 + (g>>5)].
    for (int idx = tid; idx < Tn * Gn; idx += 512) {
        const int t = idx >> 6;
        const int g = idx & 63;
        const float* xr = s_x + t * In;
        const float* wr = s_w + g * In;
        float v = s_b[g];
        #pragma unroll
        for (int i = 0; i < In; i++) v = fmaf(xr[i], wr[i], v);
        const float sc = (g < 32 || g >= 48) ? 0.5f : 1.0f;
        s_xp[t * 64 + ((g & 31) << 1) + (g >> 5)] = v * sc;
    }
    __syncthreads();

    // ---- Phase 2 (serial scan): warp 0 only ----
    // Lane L: pair-gate A = row L (i|f, sigmoid), pair-gate B = row 32+L (g|o).
    if (tid < 32) {
        const int lane = tid;
        const bool lo = lane < 16;

        // Packed, pre-scaled W_hh rows: (0.5*Wa[k], sB*Wb[k])
        const float sB = lo ? 1.0f : 0.5f;  // g: tanh(full arg); o: sigmoid(half)
        ull Wab[Hn];
        #pragma unroll
        for (int k = 0; k < Hn; k++) {
            const float wa = 0.5f * Whh[lane * Hn + k];
            const float wb = sB * Whh[(32 + lane) * Hn + k];
            Wab[k] = pack2(wa, wb);
        }

        const ull* xpp = (const ull*)s_xp;
        ull* hb_base = (ull*)s_hb;

        float h = 0.0f, c = 0.0f;
        ull xp_cur = xpp[lane];            // t = 0 pair

        for (int t = 0; t < Tn; t++) {
            // prefetch next timestep's xp pair (pad row covers t=Tn-1)
            const ull xp_next = xpp[(t + 1) * 32 + lane];

            // ---- broadcast h via smem ping-pong ----
            ull* hb = hb_base + ((t & 1) << 4);
            const ull hh = pack2(h, h);
            if (lo) hb[lane] = hh;          // 16 x STS.64
            __syncwarp();

            // ---- packed gate accumulation: (ga,gb) += (Wa,Wb)*(hk,hk) ----
            ull acc0 = xp_cur, acc1 = 0ull;
            #pragma unroll
            for (int k = 0; k < 8; k++) {
                const ulonglong2 v = ((const ulonglong2*)hb)[k];  // LDS.128 bcast
                fma2(acc0, Wab[2 * k],     v.x, acc0);
                fma2(acc1, Wab[2 * k + 1], v.y, acc1);
            }
            ull accs;
            add2(accs, acc0, acc1);
            float ga, gb;
            unpack2(ga, gb, accs);

            // ---- activations (args pre-scaled) ----
            const float Ta = tanh_apx(ga);           // -> sigmoid(i|f)
            const float Tb = tanh_apx(gb);           // lo: tanh(g); hi: -> sigmoid(o)
            const float u  = fmaf(0.5f, Ta, 0.5f);   // sigma of the A gate
            const float s1 = u * (lo ? Tb : 1.0f);   // lo: i*g ; hi: sigma(f)
            const float b2 = fmaf(0.5f, Tb, 0.5f);   // hi: sigma(o)

            // ---- cross-half exchange (2 shfls) ----
            const float r1 = __shfl_xor_sync(FULLMASK, s1, 16);
            const float r2 = __shfl_xor_sync(FULLMASK, b2, 16);
            const float fv = lo ? r1 : s1;
            const float ig = lo ? s1 : r1;
            const float ov = lo ? r2 : b2;

            c = fmaf(fv, c, ig);
            h = ov * tanh_apx(c);

            xp_cur = xp_next;
        }

        if (lo) s_h[lane] = h;
    }
    __syncthreads();

    // ---- Output: sigmoid(h_last @ W_lin.T + b_lin), 5 values ----
    if (tid < 5) {
        float v = blin[tid];
        #pragma unroll
        for (int k = 0; k < Hn; k++) v = fmaf(s_h[k], Wlin[tid * Hn + k], v);
        out[tid] = fmaf(0.5f, tanh_apx(0.5f * v), 0.5f);
    }
}

extern "C" void kernel_launch(void* const* d_in, const int* in_sizes, int n_in,
                              void* d_out, int out_size)
{
    const float *x = nullptr, *Wih = nullptr, *Whh = nullptr;
    const float *bih = nullptr, *bhh = nullptr, *Wlin = nullptr, *blin = nullptr;
    for (int i = 0; i < n_in; i++) {
        const int s = in_sizes[i];
        const float* p = (const float*)d_in[i];
        if      (s == Bn * Tn * In) x    = p;
        else if (s == Gn * In)      Wih  = p;
        else if (s == Gn * Hn)      Whh  = p;
        else if (s == 5 * Hn)       Wlin = p;
        else if (s == Gn)           { if (!bih) bih = p; else bhh = p; }
        else if (s == 5)            blin = p;
    }

    const size_t smem_bytes = (size_t)SMEM_FLOATS * sizeof(float);
    cudaFuncSetAttribute(lstm_last_kernel,
                         cudaFuncAttributeMaxDynamicSharedMemorySize,
                         (int)smem_bytes);

    lstm_last_kernel<<<1, 512, smem_bytes>>>(
        x, Wih, Whh, bih, bhh, Wlin, blin, (float*)d_out);
}

// round 4
// speedup vs baseline: 1.8246x; 1.1168x over previous
#include <cuda_runtime.h>

// LSTM_71683004170991 — only batch element B-1 contributes to the output.
// Single-warp serial scan (T=512, H=16) after parallel xp precompute.
// R4: no syncwarp (converged-warp in-order smem), hi-lane-only c/h tail
//     (zero selects, one shfl), 4-way split fma2 accumulation.

#define FULLMASK 0xffffffffu
typedef unsigned long long ull;

namespace {
constexpr int Bn = 4096;
constexpr int Tn = 512;
constexpr int In = 5;
constexpr int Hn = 16;
constexpr int Gn = 4 * Hn;  // 64

constexpr int HB_FLOATS = 64;              // 2 ping-pong bufs x 16 ull
constexpr int XP_FLOATS = (Tn + 1) * 64;   // pair rows + zero pad row
constexpr int X_ELEMS   = Tn * In;
constexpr int W_ELEMS   = Gn * In;
constexpr int SMEM_FLOATS = HB_FLOATS + XP_FLOATS + X_ELEMS + W_ELEMS + Gn + Hn;
}

__device__ __forceinline__ float tanh_apx(float x) {
    float y;
    asm("tanh.approx.f32 %0, %1;" : "=f"(y) : "f"(x));
    return y;
}
__device__ __forceinline__ void fma2(ull& d, ull a, ull b, ull c) {
    asm("fma.rn.f32x2 %0, %1, %2, %3;" : "=l"(d) : "l"(a), "l"(b), "l"(c));
}
__device__ __forceinline__ void add2(ull& d, ull a, ull b) {
    asm("add.rn.f32x2 %0, %1, %2;" : "=l"(d) : "l"(a), "l"(b));
}
__device__ __forceinline__ ull pack2(float lo, float hi) {
    ull d;
    asm("mov.b64 %0, {%1, %2};" : "=l"(d) : "f"(lo), "f"(hi));
    return d;
}
__device__ __forceinline__ void unpack2(float& lo, float& hi, ull v) {
    asm("mov.b64 {%0, %1}, %2;" : "=f"(lo), "=f"(hi) : "l"(v));
}

__global__ __launch_bounds__(512, 1)
void lstm_last_kernel(const float* __restrict__ x,
                      const float* __restrict__ Wih,
                      const float* __restrict__ Whh,
                      const float* __restrict__ bih,
                      const float* __restrict__ bhh,
                      const float* __restrict__ Wlin,
                      const float* __restrict__ blin,
                      float* __restrict__ out)
{
    extern __shared__ float smem[];
    float* s_hb = smem;                    // [2][16] (h,h) pairs
    float* s_xp = s_hb + HB_FLOATS;        // [Tn+1][32] (A,B) gate pairs
    float* s_x  = s_xp + XP_FLOATS;
    float* s_w  = s_x + X_ELEMS;
    float* s_b  = s_w + W_ELEMS;
    float* s_h  = s_b + Gn;

    const int tid = threadIdx.x;

    // ---- Stage inputs for the last batch row ----
    const float* xrow = x + (size_t)(Bn - 1) * Tn * In;
    for (int i = tid; i < X_ELEMS; i += 512) s_x[i] = xrow[i];
    for (int i = tid; i < W_ELEMS; i += 512) s_w[i] = Wih[i];
    if (tid < Gn) {
        s_b[tid] = bih[tid] + bhh[tid];
        s_xp[Tn * 64 + tid] = 0.0f;        // zero pad row for prefetch overrun
    }
    __syncthreads();

    // ---- Phase 1: xp'[t][g] = sc_g * (x_t . W_ih[g] + b_ih[g] + b_hh[g]) ----
    // PyTorch gate rows: 0..15 i, 16..31 f, 32..47 g, 48..63 o.
    // Sigmoid rows (i,f,o) pre-scaled by 0.5 for sigma(x)=0.5+0.5*tanh(x/2).
    // Pair layout: s_xp[t*64 + (g&31)*2 + (g>>5)].
    for (int idx = tid; idx < Tn * Gn; idx += 512) {
        const int t = idx >> 6;
        const int g = idx & 63;
        const float* xr = s_x + t * In;
        const float* wr = s_w + g * In;
        float v = s_b[g];
        #pragma unroll
        for (int i = 0; i < In; i++) v = fmaf(xr[i], wr[i], v);
        const float sc = (g < 32 || g >= 48) ? 0.5f : 1.0f;
        s_xp[t * 64 + ((g & 31) << 1) + (g >> 5)] = v * sc;
    }
    __syncthreads();

    // ---- Phase 2 (serial scan): warp 0 only ----
    // Lane L: A-gate = row L (i|f), B-gate = row 32+L (g|o).
    // Hi lanes (16..31, unit j=L-16) exclusively own c[j], h[j]:
    //   they hold sigma(f_j), sigma(o_j) locally and receive i_j*g_j via shfl.
    // Lo lanes' c/h registers are dead garbage; only their s1 matters.
    if (tid < 32) {
        const int lane = tid;
        const bool lo = lane < 16;

        const float sB = lo ? 1.0f : 0.5f;   // g: tanh(full); o: sigmoid(half)
        ull Wab[Hn];
        #pragma unroll
        for (int k = 0; k < Hn; k++) {
            const float wa = 0.5f * Whh[lane * Hn + k];
            const float wb = sB * Whh[(32 + lane) * Hn + k];
            Wab[k] = pack2(wa, wb);
        }

        ull* hb0 = (ull*)s_hb;
        ull* hb1 = hb0 + 16;
        const ull* xpp = (const ull*)s_xp + lane;

        float h = 0.0f, c = 0.0f;
        ull xp_cur = xpp[0];

#define STEP(HB, TNEXT)                                                   \
    {                                                                     \
        if (!lo) (HB)[lane - 16] = pack2(h, h);                           \
        asm volatile("" ::: "memory");                                    \
        const ulonglong2* hv = (const ulonglong2*)(HB);                   \
        const ulonglong2 v0 = hv[0], v1 = hv[1], v2 = hv[2], v3 = hv[3];  \
        const ulonglong2 v4 = hv[4], v5 = hv[5], v6 = hv[6], v7 = hv[7];  \
        const ull xp_next = xpp[(TNEXT) * 32];                            \
        ull a0 = xp_cur, a1 = 0ull, a2 = 0ull, a3 = 0ull;                 \
        fma2(a0, Wab[0],  v0.x, a0);  fma2(a1, Wab[1],  v0.y, a1);        \
        fma2(a2, Wab[2],  v1.x, a2);  fma2(a3, Wab[3],  v1.y, a3);        \
        fma2(a0, Wab[4],  v2.x, a0);  fma2(a1, Wab[5],  v2.y, a1);        \
        fma2(a2, Wab[6],  v3.x, a2);  fma2(a3, Wab[7],  v3.y, a3);        \
        fma2(a0, Wab[8],  v4.x, a0);  fma2(a1, Wab[9],  v4.y, a1);        \
        fma2(a2, Wab[10], v5.x, a2);  fma2(a3, Wab[11], v5.y, a3);        \
        fma2(a0, Wab[12], v6.x, a0);  fma2(a1, Wab[13], v6.y, a1);        \
        fma2(a2, Wab[14], v7.x, a2);  fma2(a3, Wab[15], v7.y, a3);        \
        add2(a0, a0, a2);  add2(a1, a1, a3);  add2(a0, a0, a1);           \
        float ga, gb;                                                     \
        unpack2(ga, gb, a0);                                              \
        const float Ta = tanh_apx(ga);          /* -> sigma(i|f) */       \
        const float u  = fmaf(0.5f, Ta, 0.5f);                            \
        const float Tb = tanh_apx(gb);          /* tanh(g) | ->sigma(o)*/ \
        const float s1 = u * Tb;                /* lo: i*g; hi: junk */   \
        const float b2 = fmaf(0.5f, Tb, 0.5f);  /* hi: sigma(o) */        \
        const float r1 = __shfl_xor_sync(FULLMASK, s1, 16);               \
        c = fmaf(u, c, r1);                     /* hi: f*c + i*g */       \
        h = b2 * tanh_apx(c);                   /* hi: o*tanh(c) */       \
        xp_cur = xp_next;                                                 \
    }

        for (int t = 0; t < Tn; t += 2) {
            STEP(hb0, t + 1);
            STEP(hb1, t + 2);   // t=510 -> prefetch pad row Tn (zeros)
        }
#undef STEP

        if (!lo) s_h[lane - 16] = h;
    }
    __syncthreads();

    // ---- Output: sigmoid(h_last @ W_lin.T + b_lin), 5 values ----
    if (tid < 5) {
        float v = blin[tid];
        #pragma unroll
        for (int k = 0; k < Hn; k++) v = fmaf(s_h[k], Wlin[tid * Hn + k], v);
        out[tid] = fmaf(0.5f, tanh_apx(0.5f * v), 0.5f);
    }
}

extern "C" void kernel_launch(void* const* d_in, const int* in_sizes, int n_in,
                              void* d_out, int out_size)
{
    const float *x = nullptr, *Wih = nullptr, *Whh = nullptr;
    const float *bih = nullptr, *bhh = nullptr, *Wlin = nullptr, *blin = nullptr;
    for (int i = 0; i < n_in; i++) {
        const int s = in_sizes[i];
        const float* p = (const float*)d_in[i];
        if      (s == Bn * Tn * In) x    = p;
        else if (s == Gn * In)      Wih  = p;
        else if (s == Gn * Hn)      Whh  = p;
        else if (s == 5 * Hn)       Wlin = p;
        else if (s == Gn)           { if (!bih) bih = p; else bhh = p; }
        else if (s == 5)            blin = p;
    }

    const size_t smem_bytes = (size_t)SMEM_FLOATS * sizeof(float);
    cudaFuncSetAttribute(lstm_last_kernel,
                         cudaFuncAttributeMaxDynamicSharedMemorySize,
                         (int)smem_bytes);

    lstm_last_kernel<<<1, 512, smem_bytes>>>(
        x, Wih, Whh, bih, bhh, Wlin, blin, (float*)d_out);
}

// round 5
// speedup vs baseline: 1.9988x; 1.0955x over previous
#include <cuda_runtime.h>

// LSTM_71683004170991 — only batch element B-1 contributes to the output.
// Single-warp serial scan (T=512, H=16) after parallel xp precompute.
// R5: lo-lane c/h ownership (shfl sigma(f)/sigma(o) early instead of s1 late),
//     unduplicated h broadcast (STS.32 + 4x LDS.128), paired-h fma2 with
//     xp seeded into accumulators during the load shadow.

#define FULLMASK 0xffffffffu
typedef unsigned long long ull;

namespace {
constexpr int Bn = 4096;
constexpr int Tn = 512;
constexpr int In = 5;
constexpr int Hn = 16;
constexpr int Gn = 4 * Hn;  // 64

constexpr int HB_FLOATS = 32;              // 2 ping-pong bufs x 16 floats
constexpr int XP_FLOATS = (Tn + 1) * 64;   // pair rows + zero pad row
constexpr int X_ELEMS   = Tn * In;
constexpr int W_ELEMS   = Gn * In;
constexpr int SMEM_FLOATS = HB_FLOATS + XP_FLOATS + X_ELEMS + W_ELEMS + Gn + Hn;
}

__device__ __forceinline__ float tanh_apx(float x) {
    float y;
    asm("tanh.approx.f32 %0, %1;" : "=f"(y) : "f"(x));
    return y;
}
__device__ __forceinline__ void fma2(ull& d, ull a, ull b, ull c) {
    asm("fma.rn.f32x2 %0, %1, %2, %3;" : "=l"(d) : "l"(a), "l"(b), "l"(c));
}
__device__ __forceinline__ void add2(ull& d, ull a, ull b) {
    asm("add.rn.f32x2 %0, %1, %2;" : "=l"(d) : "l"(a), "l"(b));
}
__device__ __forceinline__ ull pack2(float lo, float hi) {
    ull d;
    asm("mov.b64 %0, {%1, %2};" : "=l"(d) : "f"(lo), "f"(hi));
    return d;
}
__device__ __forceinline__ void unpack2(float& lo, float& hi, ull v) {
    asm("mov.b64 {%0, %1}, %2;" : "=f"(lo), "=f"(hi) : "l"(v));
}

__global__ __launch_bounds__(512, 1)
void lstm_last_kernel(const float* __restrict__ x,
                      const float* __restrict__ Wih,
                      const float* __restrict__ Whh,
                      const float* __restrict__ bih,
                      const float* __restrict__ bhh,
                      const float* __restrict__ Wlin,
                      const float* __restrict__ blin,
                      float* __restrict__ out)
{
    extern __shared__ float smem[];
    float* s_hb = smem;                    // [2][16] h floats (unduplicated)
    float* s_xp = s_hb + HB_FLOATS;        // [Tn+1][32] (A,B) gate pairs
    float* s_x  = s_xp + XP_FLOATS;
    float* s_w  = s_x + X_ELEMS;
    float* s_b  = s_w + W_ELEMS;
    float* s_h  = s_b + Gn;

    const int tid = threadIdx.x;

    // ---- Stage inputs for the last batch row ----
    const float* xrow = x + (size_t)(Bn - 1) * Tn * In;
    for (int i = tid; i < X_ELEMS; i += 512) s_x[i] = xrow[i];
    for (int i = tid; i < W_ELEMS; i += 512) s_w[i] = Wih[i];
    if (tid < Gn) {
        s_b[tid] = bih[tid] + bhh[tid];
        s_xp[Tn * 64 + tid] = 0.0f;        // zero pad row for prefetch overrun
    }
    __syncthreads();

    // ---- Phase 1: xp'[t][g] = sc_g * (x_t . W_ih[g] + b_ih[g] + b_hh[g]) ----
    // PyTorch gate rows: 0..15 i, 16..31 f, 32..47 g, 48..63 o.
    // Sigmoid rows (i,f,o) pre-scaled by 0.5: sigma(x)=0.5+0.5*tanh(x/2).
    // Pair layout: s_xp[t*64 + (g&31)*2 + (g>>5)].
    for (int idx = tid; idx < Tn * Gn; idx += 512) {
        const int t = idx >> 6;
        const int g = idx & 63;
        const float* xr = s_x + t * In;
        const float* wr = s_w + g * In;
        float v = s_b[g];
        #pragma unroll
        for (int i = 0; i < In; i++) v = fmaf(xr[i], wr[i], v);
        const float sc = (g < 32 || g >= 48) ? 0.5f : 1.0f;
        s_xp[t * 64 + ((g & 31) << 1) + (g >> 5)] = v * sc;
    }
    __syncthreads();

    // ---- Phase 2 (serial scan): warp 0 only ----
    // Lane L: A-gate = row L (i|f), B-gate = row 32+L (g|o).
    // LO lanes (0..15, unit j=L) own c[j], h[j]: they hold sigma(i), tanh(g)
    // locally and receive sigma(f), sigma(o) via early shfls from hi lanes.
    // Hi lanes' c/h registers are dead garbage.
    if (tid < 32) {
        const int lane = tid;
        const bool lo = lane < 16;

        // Paired-h weights: WA[m] = (sA*Wa[2m], sA*Wa[2m+1]) etc.
        const float sB = lo ? 1.0f : 0.5f;   // g: tanh(full); o: sigmoid(half)
        ull WA[8], WB[8];
        #pragma unroll
        for (int m = 0; m < 8; m++) {
            WA[m] = pack2(0.5f * Whh[lane * Hn + 2 * m],
                          0.5f * Whh[lane * Hn + 2 * m + 1]);
            WB[m] = pack2(sB * Whh[(32 + lane) * Hn + 2 * m],
                          sB * Whh[(32 + lane) * Hn + 2 * m + 1]);
        }

        float* hb0 = s_hb;
        float* hb1 = s_hb + 16;
        const ull* xpp = (const ull*)s_xp + lane;

        float h = 0.0f, c = 0.0f;
        float xa, xb;
        unpack2(xa, xb, xpp[0]);

#define STEP(HB, TNEXT)                                                    \
    {                                                                      \
        if (lo) (HB)[lane] = h;                                            \
        asm volatile("" ::: "memory");                                     \
        const ulonglong2* hv = (const ulonglong2*)(HB);                    \
        const ulonglong2 q0 = hv[0], q1 = hv[1], q2 = hv[2], q3 = hv[3];   \
        const ull xp_next = xpp[(TNEXT) * 32];                             \
        ull a0 = pack2(xa, 0.0f), a1 = 0ull;                               \
        ull b0 = pack2(xb, 0.0f), b1 = 0ull;                               \
        fma2(a0, WA[0], q0.x, a0);  fma2(b0, WB[0], q0.x, b0);             \
        fma2(a1, WA[1], q0.y, a1);  fma2(b1, WB[1], q0.y, b1);             \
        fma2(a0, WA[2], q1.x, a0);  fma2(b0, WB[2], q1.x, b0);             \
        fma2(a1, WA[3], q1.y, a1);  fma2(b1, WB[3], q1.y, b1);             \
        fma2(a0, WA[4], q2.x, a0);  fma2(b0, WB[4], q2.x, b0);             \
        fma2(a1, WA[5], q2.y, a1);  fma2(b1, WB[5], q2.y, b1);             \
        fma2(a0, WA[6], q3.x, a0);  fma2(b0, WB[6], q3.x, b0);             \
        fma2(a1, WA[7], q3.y, a1);  fma2(b1, WB[7], q3.y, b1);             \
        add2(a0, a0, a1);  add2(b0, b0, b1);                               \
        float Axx, Ayy, Bxx, Byy;                                          \
        unpack2(Axx, Ayy, a0);  unpack2(Bxx, Byy, b0);                     \
        const float ga = Axx + Ayy;                                        \
        const float gb = Bxx + Byy;                                        \
        const float Ta = tanh_apx(ga);           /* lo: ->si ; hi: ->sf */ \
        const float u  = fmaf(0.5f, Ta, 0.5f);                             \
        const float ru = __shfl_xor_sync(FULLMASK, u, 16); /* lo: sf */    \
        const float Tb = tanh_apx(gb);           /* lo: tanh g; hi:->so */ \
        const float b2 = fmaf(0.5f, Tb, 0.5f);                             \
        const float rb = __shfl_xor_sync(FULLMASK, b2, 16); /* lo: so */   \
        const float ig = u * Tb;                 /* lo: si * tanh g */     \
        c = fmaf(ru, c, ig);                     /* lo: sf*c + ig */       \
        h = rb * tanh_apx(c);                    /* lo: so*tanh c */       \
        unpack2(xa, xb, xp_next);                                          \
    }

        for (int t = 0; t < Tn; t += 2) {
            STEP(hb0, t + 1);
            STEP(hb1, t + 2);   // t=510 -> prefetch pad row Tn (zeros)
        }
#undef STEP

        if (lo) s_h[lane] = h;
    }
    __syncthreads();

    // ---- Output: sigmoid(h_last @ W_lin.T + b_lin), 5 values ----
    if (tid < 5) {
        float v = blin[tid];
        #pragma unroll
        for (int k = 0; k < Hn; k++) v = fmaf(s_h[k], Wlin[tid * Hn + k], v);
        out[tid] = fmaf(0.5f, tanh_apx(0.5f * v), 0.5f);
    }
}

extern "C" void kernel_launch(void* const* d_in, const int* in_sizes, int n_in,
                              void* d_out, int out_size)
{
    const float *x = nullptr, *Wih = nullptr, *Whh = nullptr;
    const float *bih = nullptr, *bhh = nullptr, *Wlin = nullptr, *blin = nullptr;
    for (int i = 0; i < n_in; i++) {
        const int s = in_sizes[i];
        const float* p = (const float*)d_in[i];
        if      (s == Bn * Tn * In) x    = p;
        else if (s == Gn * In)      Wih  = p;
        else if (s == Gn * Hn)      Whh  = p;
        else if (s == 5 * Hn)       Wlin = p;
        else if (s == Gn)           { if (!bih) bih = p; else bhh = p; }
        else if (s == 5)            blin = p;
    }

    const size_t smem_bytes = (size_t)SMEM_FLOATS * sizeof(float);
    cudaFuncSetAttribute(lstm_last_kernel,
                         cudaFuncAttributeMaxDynamicSharedMemorySize,
                         (int)smem_bytes);

    lstm_last_kernel<<<1, 512, smem_bytes>>>(
        x, Wih, Whh, bih, bhh, Wlin, blin, (float*)d_out);
}